// round 5
// baseline (speedup 1.0000x reference)
#include <cuda_runtime.h>

#define NT 512
#define NW 16
#define ITILE 8
#define VS 66   // padded V row stride (floats); even -> 8B-aligned float2 rows

// shared layout (float offsets)
#define OFF_V    0        // 416 x 66 = 27456 (xr then V in-place; rows 400..415 zeroed)
#define OFF_WV   27456    // 4096: Wv
#define OFF_AE   31552    // 800: exp(s_src)      [2][400]
#define OFF_CE   32352    // 800: exp(0.2 s_src)  [2][400]
#define OFF_BE   33152    // 800: exp(s_dst)      [2][400]
#define OFF_DE   33952    // 800: exp(0.2 s_dst)  [2][400]
#define OFF_UW   34752    // 256
#define OFF_SCR  35008    // 16 warps x 1152 (p staging: 32 records x 36 floats)
#define SMEM_FLOATS 53440
#define SMEM_BYTES (SMEM_FLOATS * 4)   // 213760 B

typedef unsigned long long ull;

__device__ __forceinline__ void fma2(ull& d, ull a, ull b) {
  asm("fma.rn.f32x2 %0, %1, %2, %0;" : "+l"(d) : "l"(a), "l"(b));
}
__device__ __forceinline__ float2 unpack2(ull v) {
  float2 f; asm("mov.b64 {%0,%1}, %2;" : "=f"(f.x), "=f"(f.y) : "l"(v)); return f;
}

__device__ float g_uw[256];

__global__ void gat_prep(const float* __restrict__ Wq, const float* __restrict__ Wk,
                         const float* __restrict__ a_src, const float* __restrict__ a_dst) {
  int tid = threadIdx.x;
  int part = tid >> 6;            // 0,1: u(h0,h1); 2,3: w(h0,h1)
  int h = part & 1;
  int c = tid & 63;
  const float* W = (part < 2) ? Wq : Wk;
  const float* a = (part < 2) ? a_src : a_dst;
  float s = 0.f;
#pragma unroll
  for (int d = 0; d < 32; ++d) s += W[(h * 32 + d) * 64 + c] * a[h * 32 + d];
  g_uw[tid] = s;
}

__global__ void __launch_bounds__(NT, 1)
gat_main(const float* __restrict__ x, const float* __restrict__ Wv,
         const int* __restrict__ gso, const float* __restrict__ ln_g,
         const float* __restrict__ ln_b, float* __restrict__ out) {
  extern __shared__ float sm[];
  float* sV  = sm + OFF_V;
  float* sWv = sm + OFF_WV;
  float* sAe = sm + OFF_AE;
  float* sCe = sm + OFF_CE;
  float* sBe = sm + OFF_BE;
  float* sDe = sm + OFF_DE;
  float* sUW = sm + OFF_UW;
  float* sScr = sm + OFF_SCR;

  const int tid = threadIdx.x;
  const int bt = blockIdx.x;
  const int b = bt >> 5, t = bt & 31;
  const float* xbt = x + (size_t)b * 819200 + (size_t)t * 400;  // [c*12800 + n]

  for (int i = tid; i < 4096; i += NT) sWv[i] = Wv[i];
  for (int i = tid; i < 256; i += NT) sUW[i] = g_uw[i];
  for (int i = tid; i < 16 * VS; i += NT) sV[400 * VS + i] = 0.f;  // zero pad rows

  // stage xr[n,c]; coalesced over n
  for (int idx = tid; idx < 25600; idx += NT) {
    int c = idx / 400;
    int n = idx - c * 400;
    sV[n * VS + c] = xbt[(size_t)c * 12800 + n];
  }
  __syncthreads();

  // ---- Phase A: scores (f32x2) + in-place V projection (f32x2) ----
  if (tid < 400) {
    const int row = tid;
    ull xr2[32];
    const ull* row8 = (const ull*)(sV + row * VS);
#pragma unroll
    for (int q = 0; q < 32; ++q) xr2[q] = row8[q];

    const ull* uw2 = (const ull*)sUW;
    ull a0 = 0, a1 = 0, a2 = 0, a3 = 0;
#pragma unroll
    for (int q = 0; q < 32; ++q) {
      fma2(a0, xr2[q], uw2[q]);
      fma2(a1, xr2[q], uw2[32 + q]);
      fma2(a2, xr2[q], uw2[64 + q]);
      fma2(a3, xr2[q], uw2[96 + q]);
    }
    float2 f0 = unpack2(a0), f1 = unpack2(a1), f2 = unpack2(a2), f3 = unpack2(a3);
    float s0 = f0.x + f0.y, s1 = f1.x + f1.y;   // src scores (h0,h1)
    float d0 = f2.x + f2.y, d1 = f3.x + f3.y;   // dst scores

    sAe[row] = __expf(s0);        sAe[400 + row] = __expf(s1);
    sCe[row] = __expf(0.2f * s0); sCe[400 + row] = __expf(0.2f * s1);
    sBe[row] = __expf(d0);        sBe[400 + row] = __expf(d1);
    sDe[row] = __expf(0.2f * d0); sDe[400 + row] = __expf(0.2f * d1);

    const ulonglong2* wv2 = (const ulonglong2*)sWv;
#pragma unroll 2
    for (int cp = 0; cp < 64; ++cp) {
      ull pa = 0, pb = 0;
#pragma unroll
      for (int q = 0; q < 16; ++q) {
        ulonglong2 w = wv2[cp * 16 + q];   // broadcast
        fma2(pa, xr2[2 * q],     w.x);
        fma2(pb, xr2[2 * q + 1], w.y);
      }
      float2 fa = unpack2(pa), fb = unpack2(pb);
      sV[row * VS + cp] = (fa.x + fa.y) + (fb.x + fb.y);  // in-place (row in regs)
    }
  }
  __syncthreads();

  // ---- Phase B: attention + LayerNorm + transposed store ----
  // lane owns channels c0=2*lane, c1=2*lane+1 (both in head h = lane>=16)
  const int warp = tid >> 5, lane = tid & 31;
  float* pS = sScr + warp * 1152;                // 32 records x 36 floats
  const int hsel = (lane < 16) ? 0 : 16;         // my head's 16-float dup block
  const float g0 = ln_g[2 * lane], g1 = ln_g[2 * lane + 1];
  const float bb0 = ln_b[2 * lane], bb1 = ln_b[2 * lane + 1];
  float* obase = out + (size_t)b * 819200 + (size_t)t * 400;

  for (int i0 = warp * ITILE; i0 < 400; i0 += NW * ITILE) {
    float A0[ITILE], A1[ITILE], C0[ITILE], C1[ITILE];
#pragma unroll
    for (int ii = 0; ii < ITILE; ++ii) {
      A0[ii] = sAe[i0 + ii]; A1[ii] = sAe[400 + i0 + ii];
      C0[ii] = sCe[i0 + ii]; C1[ii] = sCe[400 + i0 + ii];
    }
    ull acc2[ITILE]; float z0[ITILE], z1[ITILE];
#pragma unroll
    for (int ii = 0; ii < ITILE; ++ii) { acc2[ii] = 0ull; z0[ii] = z1[ii] = 0.f; }

    int gv[ITILE];
#pragma unroll
    for (int ii = 0; ii < ITILE; ++ii) gv[ii] = gso[(i0 + ii) * 400 + lane];

#pragma unroll 1
    for (int j0 = 0; j0 < 400; j0 += 32) {
      int j = j0 + lane;
      bool jv = j < 400;
      float Bv0 = 0.f, Bv1 = 0.f, Dv0 = 0.f, Dv1 = 0.f;
      if (jv) {
        Bv0 = sBe[j]; Bv1 = sBe[400 + j];
        Dv0 = sDe[j]; Dv1 = sDe[400 + j];
      }
      float p0[ITILE], p1[ITILE];
#pragma unroll
      for (int ii = 0; ii < ITILE; ++ii) {
        // e>=0  <=>  exp(s_i)*exp(s_j) >= 1 ; both branches equal 1 at boundary
        float t0 = A0[ii] * Bv0, u0 = C0[ii] * Dv0;
        float t1 = A1[ii] * Bv1, u1 = C1[ii] * Dv1;
        float q0 = (t0 >= 1.f) ? t0 : u0;
        float q1 = (t1 >= 1.f) ? t1 : u1;
        float m = gv[ii] ? 1.f : 0.f;
        p0[ii] = m * q0; p1[ii] = m * q1;
        z0[ii] += p0[ii]; z1[ii] += p1[ii];
      }
      // prefetch next gso block under the k-loop
      if (j0 + 32 < 400) {
        int j2 = j0 + 32 + lane;
        bool jv2 = j2 < 400;
#pragma unroll
        for (int ii = 0; ii < ITILE; ++ii)
          gv[ii] = jv2 ? gso[(i0 + ii) * 400 + j2] : 0;
      }
      __syncwarp();   // previous k-loop reads done before overwriting staging
      {
        float4* pw = (float4*)(pS + lane * 36);  // conflict-free (4i mod 32 pattern)
        pw[0] = make_float4(p0[0], p0[0], p0[1], p0[1]);
        pw[1] = make_float4(p0[2], p0[2], p0[3], p0[3]);
        pw[2] = make_float4(p0[4], p0[4], p0[5], p0[5]);
        pw[3] = make_float4(p0[6], p0[6], p0[7], p0[7]);
        pw[4] = make_float4(p1[0], p1[0], p1[1], p1[1]);
        pw[5] = make_float4(p1[2], p1[2], p1[3], p1[3]);
        pw[6] = make_float4(p1[4], p1[4], p1[5], p1[5]);
        pw[7] = make_float4(p1[6], p1[6], p1[7], p1[7]);
      }
      __syncwarp();
      const float* vrow = sV + j0 * VS + 2 * lane;
#pragma unroll 4
      for (int k = 0; k < 32; ++k) {
        ull v = *(const ull*)(vrow + k * VS);               // (v_c0, v_c1)
        const ulonglong2* pr = (const ulonglong2*)(pS + k * 36 + hsel);
        ulonglong2 x0 = pr[0], x1 = pr[1];                  // (p,p) duplicated pairs
        fma2(acc2[0], x0.x, v); fma2(acc2[1], x0.y, v);
        fma2(acc2[2], x1.x, v); fma2(acc2[3], x1.y, v);
        ulonglong2 x2 = pr[2], x3 = pr[3];
        fma2(acc2[4], x2.x, v); fma2(acc2[5], x2.y, v);
        fma2(acc2[6], x3.x, v); fma2(acc2[7], x3.y, v);
      }
    }
    // Z across lanes (lanes partitioned j)
#pragma unroll
    for (int off = 16; off > 0; off >>= 1) {
#pragma unroll
      for (int ii = 0; ii < ITILE; ++ii) {
        z0[ii] += __shfl_xor_sync(0xffffffffu, z0[ii], off);
        z1[ii] += __shfl_xor_sync(0xffffffffu, z1[ii], off);
      }
    }
    __syncwarp();   // k-loop reads of pS finished before LN staging overwrites
    // normalize + LayerNorm + stage transposed
#pragma unroll
    for (int ii = 0; ii < ITILE; ++ii) {
      float2 o = unpack2(acc2[ii]);
      float zh = (lane < 16) ? z0[ii] : z1[ii];
      float o0 = o.x / zh;
      float o1 = o.y / zh;
      float s = o0 + o1;
      float ss = o0 * o0 + o1 * o1;
#pragma unroll
      for (int off = 16; off > 0; off >>= 1) {
        s  += __shfl_xor_sync(0xffffffffu, s, off);
        ss += __shfl_xor_sync(0xffffffffu, ss, off);
      }
      float mu = s * (1.f / 64.f);
      float var = ss * (1.f / 64.f) - mu * mu;
      float rs = rsqrtf(var + 1e-5f);
      pS[(2 * lane) * 9 + ii]     = (o0 - mu) * rs * g0 + bb0;  // [c][ii], stride 9
      pS[(2 * lane + 1) * 9 + ii] = (o1 - mu) * rs * g1 + bb1;
    }
    __syncwarp();
    // transposed store: 8 lanes per channel, 8 consecutive n (32B sectors)
#pragma unroll
    for (int m = 0; m < 16; ++m) {
      int idx = m * 32 + lane;
      int c = idx >> 3;
      int ii = idx & 7;
      obase[(size_t)c * 12800 + i0 + ii] = pS[c * 9 + ii];
    }
    __syncwarp();
  }
}

extern "C" void kernel_launch(void* const* d_in, const int* in_sizes, int n_in,
                              void* d_out, int out_size) {
  const float* x      = (const float*)d_in[0];
  const float* Wq     = (const float*)d_in[1];
  const float* Wk     = (const float*)d_in[2];
  const float* Wv     = (const float*)d_in[3];
  const float* a_src  = (const float*)d_in[4];
  const float* a_dst  = (const float*)d_in[5];
  const float* ln_g   = (const float*)d_in[6];
  const float* ln_b   = (const float*)d_in[7];
  const int*   gso    = (const int*)d_in[8];
  float* out = (float*)d_out;

  cudaFuncSetAttribute(gat_main, cudaFuncAttributeMaxDynamicSharedMemorySize, SMEM_BYTES);
  gat_prep<<<1, 256>>>(Wq, Wk, a_src, a_dst);
  gat_main<<<256, NT, SMEM_BYTES>>>(x, Wv, gso, ln_g, ln_b, out);
}

// round 6
// speedup vs baseline: 2.3613x; 2.3613x over previous
#include <cuda_runtime.h>
#include <cuda_bf16.h>

// ---------------- device scratch (static: no allocation) ----------------
__device__ float g_uw[256];                                  // u/w projection vectors
__device__ __align__(16) __nv_bfloat16 g_Vhi[256 * 64 * 420]; // V transposed, hi bf16
__device__ __align__(16) __nv_bfloat16 g_Vlo[256 * 64 * 420]; // V transposed, lo bf16
__device__ __align__(16) float g_exp[256 * 8 * 400];          // Ae(h0,h1),Ce,Be,De
__device__ unsigned g_bm[400 * 16];                           // gso bitmap [i][word]

// ---------------- helpers ----------------
__device__ __forceinline__ unsigned bf2pack(float hi, float lo) {
  unsigned r;
  asm("cvt.rn.bf16x2.f32 %0, %1, %2;" : "=r"(r) : "f"(hi), "f"(lo));
  return r;
}
__device__ __forceinline__ float up_hi(unsigned r) { return __uint_as_float(r & 0xFFFF0000u); }
__device__ __forceinline__ float up_lo(unsigned r) { return __uint_as_float(r << 16); }

__device__ __forceinline__ void mma16816(float* c, const unsigned* a, unsigned b0, unsigned b1) {
  asm volatile(
      "mma.sync.aligned.m16n8k16.row.col.f32.bf16.bf16.f32 "
      "{%0,%1,%2,%3}, {%4,%5,%6,%7}, {%8,%9}, {%0,%1,%2,%3};"
      : "+f"(c[0]), "+f"(c[1]), "+f"(c[2]), "+f"(c[3])
      : "r"(a[0]), "r"(a[1]), "r"(a[2]), "r"(a[3]), "r"(b0), "r"(b1));
}

// ---------------- kernel 0: projection vectors ----------------
__global__ void gat_prep(const float* __restrict__ Wq, const float* __restrict__ Wk,
                         const float* __restrict__ a_src, const float* __restrict__ a_dst) {
  int tid = threadIdx.x;
  int part = tid >> 6;            // 0,1: u(h0,h1)  2,3: w(h0,h1)
  int h = part & 1;
  int c = tid & 63;
  const float* W = (part < 2) ? Wq : Wk;
  const float* a = (part < 2) ? a_src : a_dst;
  float s = 0.f;
#pragma unroll
  for (int d = 0; d < 32; ++d) s += W[(h * 32 + d) * 64 + c] * a[h * 32 + d];
  g_uw[tid] = s;
}

// ---------------- kernel 1: V projection (hi/lo bf16, transposed) + exps + bitmap ----------------
#define SM1_BYTES (107520 + 16384 + 1024)
__global__ void __launch_bounds__(512, 1)
gat_stage(const float* __restrict__ x, const float* __restrict__ Wv,
          const int* __restrict__ gso) {
  extern __shared__ char sm1[];
  __nv_bfloat16* sHi = (__nv_bfloat16*)sm1;               // [64][420]
  __nv_bfloat16* sLo = (__nv_bfloat16*)(sm1 + 53760);     // [64][420]
  float* sWv = (float*)(sm1 + 107520);                    // 4096
  float* sUW = (float*)(sm1 + 107520 + 16384);            // 256

  const int tid = threadIdx.x, bt = blockIdx.x;
  const int b = bt >> 5, t = bt & 31;

  for (int i = tid; i < 4096; i += 512) sWv[i] = Wv[i];
  for (int i = tid; i < 256; i += 512) sUW[i] = g_uw[i];

  // gso bitmap: grid-distributed warp ballots (gso shared by all graphs)
  {
    int warp = tid >> 5, lane = tid & 31;
    for (int wId = bt * 16 + warp; wId < 5200; wId += 256 * 16) {
      int r = wId / 13, wj = wId - r * 13;
      int j = wj * 32 + lane;
      int v = (j < 400) ? gso[r * 400 + j] : 0;
      unsigned m = __ballot_sync(0xffffffffu, v != 0);
      if (lane == 0) g_bm[r * 16 + wj] = m;
    }
  }
  __syncthreads();

  if (tid < 400) {
    const int j = tid;
    const float* xb = x + (size_t)b * 819200 + (size_t)t * 400 + j;
    float xr[64];
#pragma unroll
    for (int c = 0; c < 64; ++c) xr[c] = xb[(size_t)c * 12800];

    float s0 = 0.f, s1 = 0.f, d0 = 0.f, d1 = 0.f;
#pragma unroll
    for (int c = 0; c < 64; ++c) {
      float xc = xr[c];
      s0 += xc * sUW[c];       s1 += xc * sUW[64 + c];
      d0 += xc * sUW[128 + c]; d1 += xc * sUW[192 + c];
    }
    float* E = g_exp + (size_t)bt * 3200;
    E[j]        = __expf(s0);        E[400 + j]  = __expf(s1);         // Ae
    E[800 + j]  = __expf(0.2f * s0); E[1200 + j] = __expf(0.2f * s1);  // Ce
    E[1600 + j] = __expf(d0);        E[2000 + j] = __expf(d1);         // Be
    E[2400 + j] = __expf(0.2f * d0); E[2800 + j] = __expf(0.2f * d1);  // De

    const float4* wv4 = (const float4*)sWv;
#pragma unroll 2
    for (int d = 0; d < 64; ++d) {
      float a0 = 0.f, a1 = 0.f, a2 = 0.f, a3 = 0.f;
#pragma unroll
      for (int q = 0; q < 16; ++q) {
        float4 w = wv4[d * 16 + q];   // broadcast
        a0 += xr[4 * q + 0] * w.x; a1 += xr[4 * q + 1] * w.y;
        a2 += xr[4 * q + 2] * w.z; a3 += xr[4 * q + 3] * w.w;
      }
      float v = (a0 + a1) + (a2 + a3);
      __nv_bfloat16 h = __float2bfloat16(v);
      float hf = __bfloat162float(h);
      sHi[d * 420 + j] = h;
      sLo[d * 420 + j] = __float2bfloat16(v - hf);   // exact residual, then rn
    }
  }
  __syncthreads();

  float4* dh = (float4*)(g_Vhi + (size_t)bt * 26880);
  float4* dl = (float4*)(g_Vlo + (size_t)bt * 26880);
  const float4* shf = (const float4*)sHi;
  const float4* slf = (const float4*)sLo;
  for (int i = tid; i < 3360; i += 512) { dh[i] = shf[i]; dl[i] = slf[i]; }
}

// ---------------- kernel 2: MMA attention + LN + transposed store ----------------
// smem: Vhi 53760 | Vlo 53760 | E 12800 | Bit 27200 (stride 17) | LN 512
#define SM2_BYTES (53760 + 53760 + 12800 + 27200 + 512)
__global__ void __launch_bounds__(416, 1)
gat_attn(const float* __restrict__ ln_g, const float* __restrict__ ln_b,
         float* __restrict__ out) {
  extern __shared__ char sm2[];
  const __nv_bfloat16* sHi = (const __nv_bfloat16*)sm2;
  const __nv_bfloat16* sLo = (const __nv_bfloat16*)(sm2 + 53760);
  float* sE = (float*)(sm2 + 107520);
  unsigned* sBit = (unsigned*)(sm2 + 120320);
  float* sLN = (float*)(sm2 + 147520);

  const int tid = threadIdx.x, bt = blockIdx.x;
  const int b = bt >> 5, t_ = bt & 31;

  {  // prologue: gmem -> smem
    float4* v4 = (float4*)sm2;
    const float4* gh = (const float4*)(g_Vhi + (size_t)bt * 26880);
    const float4* gl = (const float4*)(g_Vlo + (size_t)bt * 26880);
    for (int i = tid; i < 3360; i += 416) { v4[i] = gh[i]; v4[3360 + i] = gl[i]; }
    const float4* ge = (const float4*)(g_exp + (size_t)bt * 3200);
    float4* e4 = (float4*)sE;
    for (int i = tid; i < 800; i += 416) e4[i] = ge[i];
    for (int i = tid; i < 6400; i += 416) sBit[(i >> 4) * 17 + (i & 15)] = g_bm[i];
    for (int i = tid; i < 64; i += 416) { sLN[i] = ln_g[i]; sLN[64 + i] = ln_b[i]; }
  }
  __syncthreads();

  const int warp = tid >> 5, lane = tid & 31;
  const int g = lane >> 2, tq = lane & 3;
  float* obase = out + (size_t)b * 819200 + (size_t)t_ * 400;

  for (int task = warp; task < 25; task += 13) {
    const int i0 = task * 16;
    const int r0 = i0 + g, r1 = r0 + 8;

    float Aer[2][2], Cer[2][2];
#pragma unroll
    for (int h = 0; h < 2; ++h) {
      Aer[h][0] = sE[h * 400 + r0];        Aer[h][1] = sE[h * 400 + r1];
      Cer[h][0] = sE[(2 + h) * 400 + r0];  Cer[h][1] = sE[(2 + h) * 400 + r1];
    }
    float C[8][4];
#pragma unroll
    for (int nt = 0; nt < 8; ++nt)
#pragma unroll
      for (int q = 0; q < 4; ++q) C[nt][q] = 0.f;
    float zz[2][2] = {{0.f, 0.f}, {0.f, 0.f}};

    for (int js = 0; js < 25; ++js) {
      const int jb = js * 16;
      unsigned w0 = sBit[r0 * 17 + (jb >> 5)] >> (jb & 16);
      unsigned w1 = sBit[r1 * 17 + (jb >> 5)] >> (jb & 16);
      const int jA = jb + 2 * tq, jB = jA + 8;
      const float m00 = (float)((w0 >> (2 * tq)) & 1u);
      const float m01 = (float)((w0 >> (2 * tq + 1)) & 1u);
      const float m02 = (float)((w0 >> (2 * tq + 8)) & 1u);
      const float m03 = (float)((w0 >> (2 * tq + 9)) & 1u);
      const float m10 = (float)((w1 >> (2 * tq)) & 1u);
      const float m11 = (float)((w1 >> (2 * tq + 1)) & 1u);
      const float m12 = (float)((w1 >> (2 * tq + 8)) & 1u);
      const float m13 = (float)((w1 >> (2 * tq + 9)) & 1u);

#pragma unroll
      for (int h = 0; h < 2; ++h) {
        const float* eb = sE + (4 + h) * 400;
        const float* ed = sE + (6 + h) * 400;
        float2 BeA = *(const float2*)(eb + jA);
        float2 BeB = *(const float2*)(eb + jB);
        float2 DeA = *(const float2*)(ed + jA);
        float2 DeB = *(const float2*)(ed + jB);
        const float A0 = Aer[h][0], A1 = Aer[h][1];
        const float Q0 = Cer[h][0], Q1 = Cer[h][1];

        // exp(lrelu(si+sj)) = (Ae*Be >= 1) ? Ae*Be : Ce*De   (factorized, verified R4/R5)
        float t00 = A0 * BeA.x, u00 = Q0 * DeA.x; float p00 = ((t00 >= 1.f) ? t00 : u00) * m00;
        float t01 = A0 * BeA.y, u01 = Q0 * DeA.y; float p01 = ((t01 >= 1.f) ? t01 : u01) * m01;
        float t02 = A0 * BeB.x, u02 = Q0 * DeB.x; float p02 = ((t02 >= 1.f) ? t02 : u02) * m02;
        float t03 = A0 * BeB.y, u03 = Q0 * DeB.y; float p03 = ((t03 >= 1.f) ? t03 : u03) * m03;
        float t10 = A1 * BeA.x, u10 = Q1 * DeA.x; float p10 = ((t10 >= 1.f) ? t10 : u10) * m10;
        float t11 = A1 * BeA.y, u11 = Q1 * DeA.y; float p11 = ((t11 >= 1.f) ? t11 : u11) * m11;
        float t12 = A1 * BeB.x, u12 = Q1 * DeB.x; float p12 = ((t12 >= 1.f) ? t12 : u12) * m12;
        float t13 = A1 * BeB.y, u13 = Q1 * DeB.y; float p13 = ((t13 >= 1.f) ? t13 : u13) * m13;

        zz[h][0] += (p00 + p01) + (p02 + p03);
        zz[h][1] += (p10 + p11) + (p12 + p13);

        // A fragments (m16n8k16): a0={r0,k0k1} a1={r1,k0k1} a2={r0,k8k9} a3={r1,k8k9}
        unsigned ah[4], al[4];
        ah[0] = bf2pack(p01, p00); ah[1] = bf2pack(p11, p10);
        ah[2] = bf2pack(p03, p02); ah[3] = bf2pack(p13, p12);
        al[0] = bf2pack(p01 - up_hi(ah[0]), p00 - up_lo(ah[0]));
        al[1] = bf2pack(p11 - up_hi(ah[1]), p10 - up_lo(ah[1]));
        al[2] = bf2pack(p03 - up_hi(ah[2]), p02 - up_lo(ah[2]));
        al[3] = bf2pack(p13 - up_hi(ah[3]), p12 - up_lo(ah[3]));

#pragma unroll
        for (int nt = 0; nt < 4; ++nt) {
          const int d = h * 32 + nt * 8 + g;
          const __nv_bfloat16* vh = sHi + d * 420;
          const __nv_bfloat16* vl = sLo + d * 420;
          unsigned bh0 = *(const unsigned*)(vh + jA);
          unsigned bh1 = *(const unsigned*)(vh + jB);
          unsigned bl0 = *(const unsigned*)(vl + jA);
          unsigned bl1 = *(const unsigned*)(vl + jB);
          float* Cp = C[h * 4 + nt];
          mma16816(Cp, ah, bh0, bh1);   // hi*hi
          mma16816(Cp, al, bh0, bh1);   // lo*hi
          mma16816(Cp, ah, bl0, bl1);   // hi*lo
        }
      }
    }

    // reduce Z over tq-lanes (k was partitioned by tq)
#pragma unroll
    for (int h = 0; h < 2; ++h)
#pragma unroll
      for (int rh = 0; rh < 2; ++rh) {
        zz[h][rh] += __shfl_xor_sync(0xffffffffu, zz[h][rh], 1);
        zz[h][rh] += __shfl_xor_sync(0xffffffffu, zz[h][rh], 2);
      }
    float rzv[2][2];
#pragma unroll
    for (int h = 0; h < 2; ++h)
#pragma unroll
      for (int rh = 0; rh < 2; ++rh) rzv[h][rh] = 1.f / zz[h][rh];

#pragma unroll
    for (int nt = 0; nt < 8; ++nt) {
      const int h = nt >> 2;
      C[nt][0] *= rzv[h][0]; C[nt][1] *= rzv[h][0];
      C[nt][2] *= rzv[h][1]; C[nt][3] *= rzv[h][1];
    }

    // LayerNorm per row (64 channels = 16 per lane x 4 tq-lanes) + store
#pragma unroll
    for (int rh = 0; rh < 2; ++rh) {
      float s = 0.f, ss = 0.f;
#pragma unroll
      for (int nt = 0; nt < 8; ++nt) {
        float o0 = C[nt][rh * 2], o1 = C[nt][rh * 2 + 1];
        s += o0 + o1; ss += o0 * o0 + o1 * o1;
      }
      s  += __shfl_xor_sync(0xffffffffu, s, 1);  s  += __shfl_xor_sync(0xffffffffu, s, 2);
      ss += __shfl_xor_sync(0xffffffffu, ss, 1); ss += __shfl_xor_sync(0xffffffffu, ss, 2);
      const float mu = s * (1.f / 64.f);
      const float var = ss * (1.f / 64.f) - mu * mu;
      const float rs = rsqrtf(var + 1e-5f);
      const int n = i0 + g + rh * 8;
#pragma unroll
      for (int nt = 0; nt < 8; ++nt) {
        const int d0 = nt * 8 + 2 * tq;
        float o0 = (C[nt][rh * 2] - mu) * rs * sLN[d0] + sLN[64 + d0];
        float o1 = (C[nt][rh * 2 + 1] - mu) * rs * sLN[d0 + 1] + sLN[64 + d0 + 1];
        obase[(size_t)d0 * 12800 + n] = o0;
        obase[(size_t)(d0 + 1) * 12800 + n] = o1;
      }
    }
  }
}

extern "C" void kernel_launch(void* const* d_in, const int* in_sizes, int n_in,
                              void* d_out, int out_size) {
  const float* x     = (const float*)d_in[0];
  const float* Wq    = (const float*)d_in[1];
  const float* Wk    = (const float*)d_in[2];
  const float* Wv    = (const float*)d_in[3];
  const float* a_src = (const float*)d_in[4];
  const float* a_dst = (const float*)d_in[5];
  const float* ln_g  = (const float*)d_in[6];
  const float* ln_b  = (const float*)d_in[7];
  const int*   gso   = (const int*)d_in[8];
  float* out = (float*)d_out;

  cudaFuncSetAttribute(gat_stage, cudaFuncAttributeMaxDynamicSharedMemorySize, SM1_BYTES);
  cudaFuncSetAttribute(gat_attn,  cudaFuncAttributeMaxDynamicSharedMemorySize, SM2_BYTES);
  gat_prep<<<1, 256>>>(Wq, Wk, a_src, a_dst);
  gat_stage<<<256, 512, SM1_BYTES>>>(x, Wv, gso);
  gat_attn<<<256, 416, SM2_BYTES>>>(ln_g, ln_b, out);
}

// round 7
// speedup vs baseline: 2.5298x; 1.0714x over previous
#include <cuda_runtime.h>
#include <cuda_bf16.h>

// ---------------- device scratch (static) ----------------
__device__ float g_uw[256];          // u/w projection vectors
__device__ unsigned g_bm[400 * 16];  // gso bitmap [i][word]

// ---------------- helpers ----------------
__device__ __forceinline__ unsigned bf2pack(float hi, float lo) {
  unsigned r;
  asm("cvt.rn.bf16x2.f32 %0, %1, %2;" : "=r"(r) : "f"(hi), "f"(lo));
  return r;
}
__device__ __forceinline__ float up_hi(unsigned r) { return __uint_as_float(r & 0xFFFF0000u); }
__device__ __forceinline__ float up_lo(unsigned r) { return __uint_as_float(r << 16); }

__device__ __forceinline__ void mma16816(float* c, const unsigned* a, unsigned b0, unsigned b1) {
  asm volatile(
      "mma.sync.aligned.m16n8k16.row.col.f32.bf16.bf16.f32 "
      "{%0,%1,%2,%3}, {%4,%5,%6,%7}, {%8,%9}, {%0,%1,%2,%3};"
      : "+f"(c[0]), "+f"(c[1]), "+f"(c[2]), "+f"(c[3])
      : "r"(a[0]), "r"(a[1]), "r"(a[2]), "r"(a[3]), "r"(b0), "r"(b1));
}

// ---------------- prep: u/w vectors + gso bitmap ----------------
__global__ void gat_prep(const float* __restrict__ Wq, const float* __restrict__ Wk,
                         const float* __restrict__ a_src, const float* __restrict__ a_dst,
                         const int* __restrict__ gso) {
  const int tid = threadIdx.x;
  if (blockIdx.x == 0 && tid < 256) {
    int part = tid >> 6;           // 0,1: u(h0,h1)  2,3: w(h0,h1)
    int h = part & 1;
    int c = tid & 63;
    const float* W = (part < 2) ? Wq : Wk;
    const float* a = (part < 2) ? a_src : a_dst;
    float s = 0.f;
#pragma unroll
    for (int d = 0; d < 32; ++d) s += W[(h * 32 + d) * 64 + c] * a[h * 32 + d];
    g_uw[tid] = s;
  }
  // bitmap: 400 rows x 13 words, distributed over all warps of all blocks
  const int warp = tid >> 5, lane = tid & 31;
  for (int wId = blockIdx.x * 8 + warp; wId < 5200; wId += gridDim.x * 8) {
    int r = wId / 13, wj = wId - r * 13;
    int j = wj * 32 + lane;
    int v = (j < 400) ? gso[r * 400 + j] : 0;
    unsigned m = __ballot_sync(0xffffffffu, v != 0);
    if (lane == 0) g_bm[r * 16 + wj] = m;
  }
}

// ---------------- fused main kernel ----------------
// smem bytes: Vhi 53760 | Vlo 53760 | E 12800 | Bit 27200 | Wv 16384 | UW 1024 | LN 512
#define OFF_HI   0
#define OFF_LO   53760
#define OFF_E    107520
#define OFF_BIT  120320
#define OFF_WVF  147520
#define OFF_UWF  163904
#define OFF_LNF  164928
#define SMF_BYTES 165440

__global__ void __launch_bounds__(800, 1)
gat_fused(const float* __restrict__ x, const float* __restrict__ Wv,
          const float* __restrict__ ln_g, const float* __restrict__ ln_b,
          float* __restrict__ out) {
  extern __shared__ char sm[];
  __nv_bfloat16* sHi = (__nv_bfloat16*)(sm + OFF_HI);   // [64][420]
  __nv_bfloat16* sLo = (__nv_bfloat16*)(sm + OFF_LO);   // [64][420]
  float* sE = (float*)(sm + OFF_E);                     // [8][400]
  unsigned* sBit = (unsigned*)(sm + OFF_BIT);           // [400][17]
  float* sWv = (float*)(sm + OFF_WVF);
  float* sUW = (float*)(sm + OFF_UWF);
  float* sLN = (float*)(sm + OFF_LNF);

  const int tid = threadIdx.x, bt = blockIdx.x;
  const int b = bt >> 5, t_ = bt & 31;

  // prologue
  for (int i = tid; i < 4096; i += 800) sWv[i] = Wv[i];
  for (int i = tid; i < 256; i += 800) sUW[i] = g_uw[i];
  for (int i = tid; i < 6400; i += 800) sBit[(i >> 4) * 17 + (i & 15)] = g_bm[i];
  for (int i = tid; i < 64; i += 800) { sLN[i] = ln_g[i]; sLN[64 + i] = ln_b[i]; }
  __syncthreads();

  // ---- Phase A: scores + V projection (row split across 2 threads by d-half) ----
  {
    const int half = (tid >= 400) ? 1 : 0;
    const int row = tid - half * 400;
    const float* xb = x + (size_t)b * 819200 + (size_t)t_ * 400 + row;
    float xr[64];
#pragma unroll
    for (int c = 0; c < 64; ++c) xr[c] = xb[(size_t)c * 12800];

    if (!half) {
      float s0 = 0.f, s1 = 0.f, d0 = 0.f, d1 = 0.f;
#pragma unroll
      for (int c = 0; c < 64; ++c) {
        float xc = xr[c];
        s0 += xc * sUW[c];       s1 += xc * sUW[64 + c];
        d0 += xc * sUW[128 + c]; d1 += xc * sUW[192 + c];
      }
      sE[row]        = __expf(s0);        sE[400 + row]  = __expf(s1);         // Ae
      sE[800 + row]  = __expf(0.2f * s0); sE[1200 + row] = __expf(0.2f * s1);  // Ce
      sE[1600 + row] = __expf(d0);        sE[2000 + row] = __expf(d1);         // Be
      sE[2400 + row] = __expf(0.2f * d0); sE[2800 + row] = __expf(0.2f * d1);  // De
    }

    const float4* wv4 = (const float4*)sWv;
    const int d0c = half * 32;
#pragma unroll 2
    for (int dd = 0; dd < 32; ++dd) {
      const int d = d0c + dd;
      float a0 = 0.f, a1 = 0.f, a2 = 0.f, a3 = 0.f;
#pragma unroll
      for (int q = 0; q < 16; ++q) {
        float4 w = wv4[d * 16 + q];   // broadcast (per half)
        a0 += xr[4 * q + 0] * w.x; a1 += xr[4 * q + 1] * w.y;
        a2 += xr[4 * q + 2] * w.z; a3 += xr[4 * q + 3] * w.w;
      }
      float v = (a0 + a1) + (a2 + a3);
      __nv_bfloat16 h = __float2bfloat16(v);
      sHi[d * 420 + row] = h;
      sLo[d * 420 + row] = __float2bfloat16(v - __bfloat162float(h));
    }
  }
  __syncthreads();

  // ---- Phase B: MMA attention + LN + transposed store (25 warps, 1 task each) ----
  const int warp = tid >> 5, lane = tid & 31;
  const int g = lane >> 2, tq = lane & 3;
  float* obase = out + (size_t)b * 819200 + (size_t)t_ * 400;

  {
    const int i0 = warp * 16;
    const int r0 = i0 + g, r1 = r0 + 8;

    float Aer[2][2], Cer[2][2];
#pragma unroll
    for (int h = 0; h < 2; ++h) {
      Aer[h][0] = sE[h * 400 + r0];        Aer[h][1] = sE[h * 400 + r1];
      Cer[h][0] = sE[(2 + h) * 400 + r0];  Cer[h][1] = sE[(2 + h) * 400 + r1];
    }
    float C[8][4];
#pragma unroll
    for (int nt = 0; nt < 8; ++nt)
#pragma unroll
      for (int q = 0; q < 4; ++q) C[nt][q] = 0.f;
    float zz[2][2] = {{0.f, 0.f}, {0.f, 0.f}};

    for (int js = 0; js < 25; ++js) {
      const int jb = js * 16;
      unsigned w0 = sBit[r0 * 17 + (jb >> 5)] >> (jb & 16);
      unsigned w1 = sBit[r1 * 17 + (jb >> 5)] >> (jb & 16);
      const int jA = jb + 2 * tq, jB = jA + 8;
      const float m00 = (float)((w0 >> (2 * tq)) & 1u);
      const float m01 = (float)((w0 >> (2 * tq + 1)) & 1u);
      const float m02 = (float)((w0 >> (2 * tq + 8)) & 1u);
      const float m03 = (float)((w0 >> (2 * tq + 9)) & 1u);
      const float m10 = (float)((w1 >> (2 * tq)) & 1u);
      const float m11 = (float)((w1 >> (2 * tq + 1)) & 1u);
      const float m12 = (float)((w1 >> (2 * tq + 8)) & 1u);
      const float m13 = (float)((w1 >> (2 * tq + 9)) & 1u);

#pragma unroll
      for (int h = 0; h < 2; ++h) {
        const float* eb = sE + (4 + h) * 400;
        const float* ed = sE + (6 + h) * 400;
        float2 BeA = *(const float2*)(eb + jA);
        float2 BeB = *(const float2*)(eb + jB);
        float2 DeA = *(const float2*)(ed + jA);
        float2 DeB = *(const float2*)(ed + jB);
        const float A0 = Aer[h][0], A1 = Aer[h][1];
        const float Q0 = Cer[h][0], Q1 = Cer[h][1];

        // exp(lrelu(si+sj)) = (Ae*Be >= 1) ? Ae*Be : Ce*De
        float t00 = A0 * BeA.x, u00 = Q0 * DeA.x; float p00 = ((t00 >= 1.f) ? t00 : u00) * m00;
        float t01 = A0 * BeA.y, u01 = Q0 * DeA.y; float p01 = ((t01 >= 1.f) ? t01 : u01) * m01;
        float t02 = A0 * BeB.x, u02 = Q0 * DeB.x; float p02 = ((t02 >= 1.f) ? t02 : u02) * m02;
        float t03 = A0 * BeB.y, u03 = Q0 * DeB.y; float p03 = ((t03 >= 1.f) ? t03 : u03) * m03;
        float t10 = A1 * BeA.x, u10 = Q1 * DeA.x; float p10 = ((t10 >= 1.f) ? t10 : u10) * m10;
        float t11 = A1 * BeA.y, u11 = Q1 * DeA.y; float p11 = ((t11 >= 1.f) ? t11 : u11) * m11;
        float t12 = A1 * BeB.x, u12 = Q1 * DeB.x; float p12 = ((t12 >= 1.f) ? t12 : u12) * m12;
        float t13 = A1 * BeB.y, u13 = Q1 * DeB.y; float p13 = ((t13 >= 1.f) ? t13 : u13) * m13;

        zz[h][0] += (p00 + p01) + (p02 + p03);
        zz[h][1] += (p10 + p11) + (p12 + p13);

        unsigned ah[4], al[4];
        ah[0] = bf2pack(p01, p00); ah[1] = bf2pack(p11, p10);
        ah[2] = bf2pack(p03, p02); ah[3] = bf2pack(p13, p12);
        al[0] = bf2pack(p01 - up_hi(ah[0]), p00 - up_lo(ah[0]));
        al[1] = bf2pack(p11 - up_hi(ah[1]), p10 - up_lo(ah[1]));
        al[2] = bf2pack(p03 - up_hi(ah[2]), p02 - up_lo(ah[2]));
        al[3] = bf2pack(p13 - up_hi(ah[3]), p12 - up_lo(ah[3]));

#pragma unroll
        for (int nt = 0; nt < 4; ++nt) {
          const int d = h * 32 + nt * 8 + g;
          const __nv_bfloat16* vh = sHi + d * 420;
          const __nv_bfloat16* vl = sLo + d * 420;
          unsigned bh0 = *(const unsigned*)(vh + jA);
          unsigned bh1 = *(const unsigned*)(vh + jB);
          unsigned bl0 = *(const unsigned*)(vl + jA);
          unsigned bl1 = *(const unsigned*)(vl + jB);
          float* Cp = C[h * 4 + nt];
          mma16816(Cp, ah, bh0, bh1);   // hi*hi
          mma16816(Cp, al, bh0, bh1);   // lo*hi
          mma16816(Cp, ah, bl0, bl1);   // hi*lo
        }
      }
    }

    // Z across tq-lanes (k partitioned by tq)
#pragma unroll
    for (int h = 0; h < 2; ++h)
#pragma unroll
      for (int rh = 0; rh < 2; ++rh) {
        zz[h][rh] += __shfl_xor_sync(0xffffffffu, zz[h][rh], 1);
        zz[h][rh] += __shfl_xor_sync(0xffffffffu, zz[h][rh], 2);
      }
    float rzv[2][2];
#pragma unroll
    for (int h = 0; h < 2; ++h)
#pragma unroll
      for (int rh = 0; rh < 2; ++rh) rzv[h][rh] = 1.f / zz[h][rh];

#pragma unroll
    for (int nt = 0; nt < 8; ++nt) {
      const int h = nt >> 2;
      C[nt][0] *= rzv[h][0]; C[nt][1] *= rzv[h][0];
      C[nt][2] *= rzv[h][1]; C[nt][3] *= rzv[h][1];
    }

    // LayerNorm per row + transposed store
#pragma unroll
    for (int rh = 0; rh < 2; ++rh) {
      float s = 0.f, ss = 0.f;
#pragma unroll
      for (int nt = 0; nt < 8; ++nt) {
        float o0 = C[nt][rh * 2], o1 = C[nt][rh * 2 + 1];
        s += o0 + o1; ss += o0 * o0 + o1 * o1;
      }
      s  += __shfl_xor_sync(0xffffffffu, s, 1);  s  += __shfl_xor_sync(0xffffffffu, s, 2);
      ss += __shfl_xor_sync(0xffffffffu, ss, 1); ss += __shfl_xor_sync(0xffffffffu, ss, 2);
      const float mu = s * (1.f / 64.f);
      const float var = ss * (1.f / 64.f) - mu * mu;
      const float rs = rsqrtf(var + 1e-5f);
      const int n = i0 + g + rh * 8;
#pragma unroll
      for (int nt = 0; nt < 8; ++nt) {
        const int d0 = nt * 8 + 2 * tq;
        float o0 = (C[nt][rh * 2] - mu) * rs * sLN[d0] + sLN[64 + d0];
        float o1 = (C[nt][rh * 2 + 1] - mu) * rs * sLN[d0 + 1] + sLN[64 + d0 + 1];
        obase[(size_t)d0 * 12800 + n] = o0;
        obase[(size_t)(d0 + 1) * 12800 + n] = o1;
      }
    }
  }
}

extern "C" void kernel_launch(void* const* d_in, const int* in_sizes, int n_in,
                              void* d_out, int out_size) {
  const float* x     = (const float*)d_in[0];
  const float* Wq    = (const float*)d_in[1];
  const float* Wk    = (const float*)d_in[2];
  const float* Wv    = (const float*)d_in[3];
  const float* a_src = (const float*)d_in[4];
  const float* a_dst = (const float*)d_in[5];
  const float* ln_g  = (const float*)d_in[6];
  const float* ln_b  = (const float*)d_in[7];
  const int*   gso   = (const int*)d_in[8];
  float* out = (float*)d_out;

  cudaFuncSetAttribute(gat_fused, cudaFuncAttributeMaxDynamicSharedMemorySize, SMF_BYTES);
  gat_prep<<<52, 256>>>(Wq, Wk, a_src, a_dst, gso);
  gat_fused<<<256, 800, SMF_BYTES>>>(x, Wv, ln_g, ln_b, out);
}

// round 8
// speedup vs baseline: 2.5347x; 1.0019x over previous
#include <cuda_runtime.h>
#include <cuda_bf16.h>

// ---------------- device scratch (static) ----------------
__device__ float g_uw[256];          // u/w projection vectors
__device__ unsigned g_bm[400 * 16];  // gso bitmap [i][word]

// ---------------- helpers ----------------
__device__ __forceinline__ unsigned bf2pack(float hi, float lo) {
  unsigned r;
  asm("cvt.rn.bf16x2.f32 %0, %1, %2;" : "=r"(r) : "f"(hi), "f"(lo));
  return r;
}
__device__ __forceinline__ float up_hi(unsigned r) { return __uint_as_float(r & 0xFFFF0000u); }
__device__ __forceinline__ float up_lo(unsigned r) { return __uint_as_float(r << 16); }

__device__ __forceinline__ void mma16816(float* c, const unsigned* a, unsigned b0, unsigned b1) {
  asm volatile(
      "mma.sync.aligned.m16n8k16.row.col.f32.bf16.bf16.f32 "
      "{%0,%1,%2,%3}, {%4,%5,%6,%7}, {%8,%9}, {%0,%1,%2,%3};"
      : "+f"(c[0]), "+f"(c[1]), "+f"(c[2]), "+f"(c[3])
      : "r"(a[0]), "r"(a[1]), "r"(a[2]), "r"(a[3]), "r"(b0), "r"(b1));
}

// ---------------- prep: u/w vectors + gso bitmap ----------------
__global__ void gat_prep(const float* __restrict__ Wq, const float* __restrict__ Wk,
                         const float* __restrict__ a_src, const float* __restrict__ a_dst,
                         const int* __restrict__ gso) {
  const int tid = threadIdx.x;
  if (blockIdx.x == 0 && tid < 256) {
    int part = tid >> 6;           // 0,1: u(h0,h1)  2,3: w(h0,h1)
    int h = part & 1;
    int c = tid & 63;
    const float* W = (part < 2) ? Wq : Wk;
    const float* a = (part < 2) ? a_src : a_dst;
    float s = 0.f;
#pragma unroll
    for (int d = 0; d < 32; ++d) s += W[(h * 32 + d) * 64 + c] * a[h * 32 + d];
    g_uw[tid] = s;
  }
  const int warp = tid >> 5, lane = tid & 31;
  for (int wId = blockIdx.x * 8 + warp; wId < 5200; wId += gridDim.x * 8) {
    int r = wId / 13, wj = wId - r * 13;
    int j = wj * 32 + lane;
    int v = (j < 400) ? gso[r * 400 + j] : 0;
    unsigned m = __ballot_sync(0xffffffffu, v != 0);
    if (lane == 0) g_bm[r * 16 + wj] = m;
  }
}

// ---------------- fused main kernel ----------------
// smem bytes: Vhi 53760 | Vlo 53760 | E 12800 | Bit 27200 | Wv 16384 | UW 1024 | LN 512
#define OFF_HI   0
#define OFF_LO   53760
#define OFF_E    107520
#define OFF_BIT  120320
#define OFF_WVF  147520
#define OFF_UWF  163904
#define OFF_LNF  164928
#define SMF_BYTES 165440

typedef unsigned long long ull;

__global__ void __launch_bounds__(800, 1)
gat_fused(const float* __restrict__ x, const float* __restrict__ Wv,
          const float* __restrict__ ln_g, const float* __restrict__ ln_b,
          float* __restrict__ out) {
  extern __shared__ char sm[];
  __nv_bfloat16* sHi = (__nv_bfloat16*)(sm + OFF_HI);   // [64][420]
  __nv_bfloat16* sLo = (__nv_bfloat16*)(sm + OFF_LO);   // [64][420]
  float* sE = (float*)(sm + OFF_E);                     // [8][400]
  unsigned* sBit = (unsigned*)(sm + OFF_BIT);           // [400][17]
  float* sWv = (float*)(sm + OFF_WVF);
  float* sUW = (float*)(sm + OFF_UWF);
  float* sLN = (float*)(sm + OFF_LNF);

  const int tid = threadIdx.x, bt = blockIdx.x;
  const int b = bt >> 5, t_ = bt & 31;

  // prologue
  for (int i = tid; i < 4096; i += 800) sWv[i] = Wv[i];
  for (int i = tid; i < 256; i += 800) sUW[i] = g_uw[i];
  for (int i = tid; i < 6400; i += 800) sBit[(i >> 4) * 17 + (i & 15)] = g_bm[i];
  for (int i = tid; i < 64; i += 800) { sLN[i] = ln_g[i]; sLN[64 + i] = ln_b[i]; }
  __syncthreads();

  // ---- Phase A: scores + V projection (row split across 2 threads by d-half) ----
  {
    const int half = (tid >= 400) ? 1 : 0;
    const int row = tid - half * 400;
    const float* xb = x + (size_t)b * 819200 + (size_t)t_ * 400 + row;
    float xr[64];
#pragma unroll
    for (int c = 0; c < 64; ++c) xr[c] = xb[(size_t)c * 12800];

    if (!half) {
      float s0 = 0.f, s1 = 0.f, d0 = 0.f, d1 = 0.f;
#pragma unroll
      for (int c = 0; c < 64; ++c) {
        float xc = xr[c];
        s0 += xc * sUW[c];       s1 += xc * sUW[64 + c];
        d0 += xc * sUW[128 + c]; d1 += xc * sUW[192 + c];
      }
      sE[row]        = __expf(s0);        sE[400 + row]  = __expf(s1);         // Ae
      sE[800 + row]  = __expf(0.2f * s0); sE[1200 + row] = __expf(0.2f * s1);  // Ce
      sE[1600 + row] = __expf(d0);        sE[2000 + row] = __expf(d1);         // Be
      sE[2400 + row] = __expf(0.2f * d0); sE[2800 + row] = __expf(0.2f * d1);  // De
    }

    const float4* wv4 = (const float4*)sWv;
    const int d0c = half * 32;
#pragma unroll 2
    for (int dd = 0; dd < 32; ++dd) {
      const int d = d0c + dd;
      float a0 = 0.f, a1 = 0.f, a2 = 0.f, a3 = 0.f;
#pragma unroll
      for (int q = 0; q < 16; ++q) {
        float4 w = wv4[d * 16 + q];   // broadcast (per half)
        a0 += xr[4 * q + 0] * w.x; a1 += xr[4 * q + 1] * w.y;
        a2 += xr[4 * q + 2] * w.z; a3 += xr[4 * q + 3] * w.w;
      }
      float v = (a0 + a1) + (a2 + a3);
      __nv_bfloat16 h = __float2bfloat16(v);
      sHi[d * 420 + row] = h;
      sLo[d * 420 + row] = __float2bfloat16(v - __bfloat162float(h));
    }
  }
  __syncthreads();

  // ---- Phase B: MMA attention + LN + transposed store (25 warps, 1 task each) ----
  // k-permutation: MMA-k {2tq,2tq+1} -> j {jb+4tq, +1}; {2tq+8,2tq+9} -> j {jb+4tq+2, +3}
  const int warp = tid >> 5, lane = tid & 31;
  const int g = lane >> 2, tq = lane & 3;
  float* obase = out + (size_t)b * 819200 + (size_t)t_ * 400;

  {
    const int i0 = warp * 16;
    const int r0 = i0 + g, r1 = r0 + 8;

    float Aer[2][2], Cer[2][2];
#pragma unroll
    for (int h = 0; h < 2; ++h) {
      Aer[h][0] = sE[h * 400 + r0];        Aer[h][1] = sE[h * 400 + r1];
      Cer[h][0] = sE[(2 + h) * 400 + r0];  Cer[h][1] = sE[(2 + h) * 400 + r1];
    }
    float C[8][4];
#pragma unroll
    for (int nt = 0; nt < 8; ++nt)
#pragma unroll
      for (int q = 0; q < 4; ++q) C[nt][q] = 0.f;
    float Cz[2][4];
#pragma unroll
    for (int h = 0; h < 2; ++h)
#pragma unroll
      for (int q = 0; q < 4; ++q) Cz[h][q] = 0.f;

    for (int js = 0; js < 25; ++js) {
      const int jb = js * 16;
      const unsigned wd0 = sBit[r0 * 17 + (jb >> 5)];
      const unsigned wd1 = sBit[r1 * 17 + (jb >> 5)];
      const int sh = (jb & 16) + 4 * tq;
      const unsigned n0 = (wd0 >> sh) & 0xFu;
      const unsigned n1 = (wd1 >> sh) & 0xFu;
      unsigned mk[4];
      mk[0] = ((n0 & 1u) ? 0x0000FFFFu : 0u) | ((n0 & 2u) ? 0xFFFF0000u : 0u);
      mk[1] = ((n1 & 1u) ? 0x0000FFFFu : 0u) | ((n1 & 2u) ? 0xFFFF0000u : 0u);
      mk[2] = ((n0 & 4u) ? 0x0000FFFFu : 0u) | ((n0 & 8u) ? 0xFFFF0000u : 0u);
      mk[3] = ((n1 & 4u) ? 0x0000FFFFu : 0u) | ((n1 & 8u) ? 0xFFFF0000u : 0u);
      const int j4 = jb + 4 * tq;

#pragma unroll
      for (int h = 0; h < 2; ++h) {
        const float4 Be = *(const float4*)(sE + (4 + h) * 400 + j4);
        const float4 De = *(const float4*)(sE + (6 + h) * 400 + j4);
        const float A0 = Aer[h][0], A1 = Aer[h][1];
        const float Q0 = Cer[h][0], Q1 = Cer[h][1];

        // exp(lrelu(si+sj)) = max(Ae*Be, Ce*De)  [e^e >= e^{0.2e} <=> e>=0]
        const float p00 = fmaxf(A0 * Be.x, Q0 * De.x);
        const float p01 = fmaxf(A0 * Be.y, Q0 * De.y);
        const float p02 = fmaxf(A0 * Be.z, Q0 * De.z);
        const float p03 = fmaxf(A0 * Be.w, Q0 * De.w);
        const float p10 = fmaxf(A1 * Be.x, Q1 * De.x);
        const float p11 = fmaxf(A1 * Be.y, Q1 * De.y);
        const float p12 = fmaxf(A1 * Be.z, Q1 * De.z);
        const float p13 = fmaxf(A1 * Be.w, Q1 * De.w);

        // raw hi/lo packs, then mask by AND (masked halves become +0.0)
        const unsigned h0 = bf2pack(p01, p00);
        const unsigned h1 = bf2pack(p11, p10);
        const unsigned h2 = bf2pack(p03, p02);
        const unsigned h3 = bf2pack(p13, p12);
        unsigned ah[4], al[4];
        al[0] = bf2pack(p01 - up_hi(h0), p00 - up_lo(h0)) & mk[0];
        al[1] = bf2pack(p11 - up_hi(h1), p10 - up_lo(h1)) & mk[1];
        al[2] = bf2pack(p03 - up_hi(h2), p02 - up_lo(h2)) & mk[2];
        al[3] = bf2pack(p13 - up_hi(h3), p12 - up_lo(h3)) & mk[3];
        ah[0] = h0 & mk[0]; ah[1] = h1 & mk[1];
        ah[2] = h2 & mk[2]; ah[3] = h3 & mk[3];

        // Z via constant-ones B fragment (bf16 1.0 = 0x3F80): every C col = row-sum
        mma16816(Cz[h], ah, 0x3F803F80u, 0x3F803F80u);
        mma16816(Cz[h], al, 0x3F803F80u, 0x3F803F80u);

#pragma unroll
        for (int nt = 0; nt < 4; ++nt) {
          const int d = h * 32 + nt * 8 + g;
          const ull bh = *(const ull*)(sHi + d * 420 + j4);
          const ull bl = *(const ull*)(sLo + d * 420 + j4);
          float* Cp = C[h * 4 + nt];
          mma16816(Cp, ah, (unsigned)bh, (unsigned)(bh >> 32));  // hi*hi
          mma16816(Cp, al, (unsigned)bh, (unsigned)(bh >> 32));  // lo*hi
          mma16816(Cp, ah, (unsigned)bl, (unsigned)(bl >> 32));  // hi*lo
        }
      }
    }

    // normalize by Z (in-register: Cz[h][0]=z(r0), Cz[h][2]=z(r1), all cols equal)
    float rzv[2][2];
#pragma unroll
    for (int h = 0; h < 2; ++h) {
      rzv[h][0] = 1.f / Cz[h][0];
      rzv[h][1] = 1.f / Cz[h][2];
    }
#pragma unroll
    for (int nt = 0; nt < 8; ++nt) {
      const int h = nt >> 2;
      C[nt][0] *= rzv[h][0]; C[nt][1] *= rzv[h][0];
      C[nt][2] *= rzv[h][1]; C[nt][3] *= rzv[h][1];
    }

    // LayerNorm per row + transposed store
#pragma unroll
    for (int rh = 0; rh < 2; ++rh) {
      float s = 0.f, ss = 0.f;
#pragma unroll
      for (int nt = 0; nt < 8; ++nt) {
        float o0 = C[nt][rh * 2], o1 = C[nt][rh * 2 + 1];
        s += o0 + o1; ss += o0 * o0 + o1 * o1;
      }
      s  += __shfl_xor_sync(0xffffffffu, s, 1);  s  += __shfl_xor_sync(0xffffffffu, s, 2);
      ss += __shfl_xor_sync(0xffffffffu, ss, 1); ss += __shfl_xor_sync(0xffffffffu, ss, 2);
      const float mu = s * (1.f / 64.f);
      const float var = ss * (1.f / 64.f) - mu * mu;
      const float rs = rsqrtf(var + 1e-5f);
      const int n = i0 + g + rh * 8;
#pragma unroll
      for (int nt = 0; nt < 8; ++nt) {
        const int d0 = nt * 8 + 2 * tq;
        float o0 = (C[nt][rh * 2] - mu) * rs * sLN[d0] + sLN[64 + d0];
        float o1 = (C[nt][rh * 2 + 1] - mu) * rs * sLN[d0 + 1] + sLN[64 + d0 + 1];
        obase[(size_t)d0 * 12800 + n] = o0;
        obase[(size_t)(d0 + 1) * 12800 + n] = o1;
      }
    }
  }
}

extern "C" void kernel_launch(void* const* d_in, const int* in_sizes, int n_in,
                              void* d_out, int out_size) {
  const float* x     = (const float*)d_in[0];
  const float* Wq    = (const float*)d_in[1];
  const float* Wk    = (const float*)d_in[2];
  const float* Wv    = (const float*)d_in[3];
  const float* a_src = (const float*)d_in[4];
  const float* a_dst = (const float*)d_in[5];
  const float* ln_g  = (const float*)d_in[6];
  const float* ln_b  = (const float*)d_in[7];
  const int*   gso   = (const int*)d_in[8];
  float* out = (float*)d_out;

  cudaFuncSetAttribute(gat_fused, cudaFuncAttributeMaxDynamicSharedMemorySize, SMF_BYTES);
  gat_prep<<<52, 256>>>(Wq, Wk, a_src, a_dst, gso);
  gat_fused<<<256, 800, SMF_BYTES>>>(x, Wv, ln_g, ln_b, out);
}